// round 5
// baseline (speedup 1.0000x reference)
#include <cuda_runtime.h>

#define FULLM 0xFFFFFFFFu
#define NQ 10
#define NL 4

// 128 threads, 8 amps/thread. Amp index i (10 bits), wire q <-> bit (9-q).
// i = (w << 8) | (k << 5) | lane5, where w = tid>>5 (2 bits), k = amp slot (3 bits).
//   w bits  -> i bits 9,8  = wires 0,1   (cross-warp)
//   k bits  -> i bits 7,6,5 = wires 2,3,4 (thread-LOCAL)
//   lane    -> i bits 4..0  = wires 5..9  (warp shuffle)
// Layout B: transpose T swaps i-bits (9,4) and (8,3) -> lane holds wires 0,1(,7,8,9).

__device__ __forceinline__ constexpr int sigma_c(int src) {  // CNOT-ring gather (GF(2)-linear)
  src ^= ((src >> 0) & 1) << 9;  // (9,0)
  src ^= ((src >> 1) & 1) << 0;  // (8,9)
  src ^= ((src >> 2) & 1) << 1;  // (7,8)
  src ^= ((src >> 3) & 1) << 2;  // (6,7)
  src ^= ((src >> 4) & 1) << 3;  // (5,6)
  src ^= ((src >> 5) & 1) << 4;  // (4,5)
  src ^= ((src >> 6) & 1) << 5;  // (3,4)
  src ^= ((src >> 7) & 1) << 6;  // (2,3)
  src ^= ((src >> 8) & 1) << 7;  // (1,2)
  src ^= ((src >> 9) & 1) << 8;  // (0,1)
  return src;
}
__device__ __forceinline__ constexpr int T_c(int x) {  // swap bits 9<->4, 8<->3
  return (x & ~0x318) | ((x & 0x300) >> 5) | ((x & 0x018) << 5);
}
__device__ __forceinline__ constexpr int swz(int j) { return j ^ ((j >> 5) & 31); }
__device__ __forceinline__ constexpr int SWK(int k) { return swz(k << 5); }          // store/T offsets
__device__ __forceinline__ constexpr int SGK(int k) { return swz(sigma_c(k << 5)); } // CNOT offsets

__global__ void __launch_bounds__(128)
hqh_kernel(const float* __restrict__ x,
           const float* __restrict__ params,
           float* __restrict__ out,
           int nTok)
{
  __shared__ float bufA[1024], bufB[1024];
  __shared__ float pc[NL * NQ], ps[NL * NQ];
  __shared__ float r1[4][20];
  __shared__ float zbs[NQ], xbs[NQ];

  const int tid  = threadIdx.x;
  const int lane = tid & 31;
  const int w    = tid >> 5;

  if (tid < NL * NQ) {
    float s, c;
    __sincosf(0.5f * params[tid], &s, &c);
    pc[tid] = c; ps[tid] = s;
  }

  // ---- prologue: issue x loads early (latency hidden under prep) ----
  const int total4 = nTok * 16;
  const int stride = gridDim.x * blockDim.x;
  const int idx0 = blockIdx.x * blockDim.x + tid;
  float4 xv4[4];
  #pragma unroll
  for (int j = 0; j < 4; j++) {
    const int idx = idx0 + j * stride;
    if (idx < total4 && (idx & 15) < 3) xv4[j] = ((const float4*)x)[idx];
  }

  const int iA    = (w << 8) | lane;
  const int sSt   = swz(iA);            // store base (addr = swz(amp index))
  const int gT    = swz(T_c(iA));       // A->B transpose gather base
  const int sigAi = sigma_c(iA);
  const int gS    = swz(sigAi);         // CNOT gather base
  __syncthreads();

  float a[8];
  // ---- layer 0 closed form with its CNOT ring folded in ----
  {
    float c0[NQ], s0[NQ];
    #pragma unroll
    for (int q = 0; q < NQ; q++) { c0[q] = pc[q]; s0[q] = ps[q]; }
    #pragma unroll
    for (int k = 0; k < 8; k++) {
      const int si = sigAi ^ sigma_c(k << 5);
      float v = 1.f;
      #pragma unroll
      for (int q = 0; q < NQ; q++)
        v *= ((si >> (9 - q)) & 1) ? s0[q] : c0[q];
      a[k] = v;
    }
  }

  #pragma unroll
  for (int l = 1; l < NL; l++) {
    const float* C = pc + l * NQ;
    const float* S = ps + l * NQ;
    const float C0=C[0],S0=S[0],C1=C[1],S1=S[1],C2=C[2],S2=S[2],C3=C[3],S3=S[3],C4=C[4],S4=S[4];
    const float C5=C[5],S5=S[5],C6=C[6],S6=S[6],C7=C[7],S7=S[7],C8=C[8],S8=S[8],C9=C[9],S9=S[9];

    // local RY wires 2,3,4 (k bits 2,1,0)
    #pragma unroll
    for (int k = 0; k < 4; k++) {          // wire2: pair (k, k|4)
      float lo = a[k], hi = a[k | 4];
      a[k] = C2 * lo - S2 * hi;  a[k | 4] = fmaf(S2, lo, C2 * hi);
    }
    #pragma unroll
    for (int k = 0; k < 8; k++) if (!(k & 2)) {  // wire3: pair (k, k|2)
      float lo = a[k], hi = a[k | 2];
      a[k] = C3 * lo - S3 * hi;  a[k | 2] = fmaf(S3, lo, C3 * hi);
    }
    #pragma unroll
    for (int k = 0; k < 8; k += 2) {       // wire4: pair (k, k|1)
      float lo = a[k], hi = a[k | 1];
      a[k] = C4 * lo - S4 * hi;  a[k | 1] = fmaf(S4, lo, C4 * hi);
    }
    // lane RY wires (5,6) fused rank-4 (masks 16,8)
    {
      const float sA = (lane & 16) ? S5 : -S5;
      const float sB = (lane & 8)  ? S6 : -S6;
      const float k00 = C5 * C6, k01 = C5 * sB, k10 = sA * C6, k11 = sA * sB;
      #pragma unroll
      for (int k = 0; k < 8; k++) {
        float vB  = __shfl_xor_sync(FULLM, a[k], 8);
        float vA  = __shfl_xor_sync(FULLM, a[k], 16);
        float vAB = __shfl_xor_sync(FULLM, a[k], 24);
        a[k] = fmaf(k00, a[k], fmaf(k01, vB, fmaf(k10, vA, k11 * vAB)));
      }
    }
    // lane RY wires (7,8) fused rank-4 (masks 4,2)
    {
      const float sA = (lane & 4) ? S7 : -S7;
      const float sB = (lane & 2) ? S8 : -S8;
      const float k00 = C7 * C8, k01 = C7 * sB, k10 = sA * C8, k11 = sA * sB;
      #pragma unroll
      for (int k = 0; k < 8; k++) {
        float vB  = __shfl_xor_sync(FULLM, a[k], 2);
        float vA  = __shfl_xor_sync(FULLM, a[k], 4);
        float vAB = __shfl_xor_sync(FULLM, a[k], 6);
        a[k] = fmaf(k00, a[k], fmaf(k01, vB, fmaf(k10, vA, k11 * vAB)));
      }
    }
    // lane RY wire 9 (mask 1)
    {
      const float se = (lane & 1) ? S9 : -S9;
      #pragma unroll
      for (int k = 0; k < 8; k++) {
        float p = __shfl_xor_sync(FULLM, a[k], 1);
        a[k] = fmaf(C9, a[k], se * p);
      }
    }
    // exchange A -> B (transpose T)
    #pragma unroll
    for (int k = 0; k < 8; k++) bufA[sSt ^ SWK(k)] = a[k];
    __syncthreads();
    #pragma unroll
    for (int k = 0; k < 8; k++) a[k] = bufA[gT ^ SWK(k)];   // T(k<<5) = k<<5
    // layout B: lane RY wires (0,1) fused rank-4 (masks 16,8)
    {
      const float sA = (lane & 16) ? S0 : -S0;
      const float sB = (lane & 8)  ? S1 : -S1;
      const float k00 = C0 * C1, k01 = C0 * sB, k10 = sA * C1, k11 = sA * sB;
      #pragma unroll
      for (int k = 0; k < 8; k++) {
        float vB  = __shfl_xor_sync(FULLM, a[k], 8);
        float vA  = __shfl_xor_sync(FULLM, a[k], 16);
        float vAB = __shfl_xor_sync(FULLM, a[k], 24);
        a[k] = fmaf(k00, a[k], fmaf(k01, vB, fmaf(k10, vA, k11 * vAB)));
      }
    }
    // exchange B -> A with CNOT ring folded (store by amp index, gather via sigma)
    #pragma unroll
    for (int k = 0; k < 8; k++) bufB[gT ^ SWK(k)] = a[k];
    __syncthreads();
    #pragma unroll
    for (int k = 0; k < 8; k++) a[k] = bufB[gS ^ SGK(k)];
  }

  // ---- observables of the base state ----
  float p8[8];
  #pragma unroll
  for (int k = 0; k < 8; k++) p8[k] = a[k] * a[k];
  float ptot = 0.f;
  #pragma unroll
  for (int k = 0; k < 8; k++) ptot += p8[k];

  float red[13];
  red[0] = (p8[0]+p8[1]+p8[2]+p8[3]) - (p8[4]+p8[5]+p8[6]+p8[7]);      // z2
  red[1] = (p8[0]+p8[1]+p8[4]+p8[5]) - (p8[2]+p8[3]+p8[6]+p8[7]);      // z3
  red[2] = (p8[0]+p8[2]+p8[4]+p8[6]) - (p8[1]+p8[3]+p8[5]+p8[7]);      // z4
  // x0, x1 via bufB partner loads (constexpr offsets)
  {
    float x0p = 0.f, x1p = 0.f;
    const int o0 = swz(sigma_c(0x200));
    const int o1 = swz(sigma_c(0x100));
    #pragma unroll
    for (int k = 0; k < 8; k++) {
      x0p = fmaf(a[k], bufB[gS ^ SGK(k) ^ o0], x0p);
      x1p = fmaf(a[k], bufB[gS ^ SGK(k) ^ o1], x1p);
    }
    red[3] = x0p; red[4] = x1p;
  }
  // x2,x3,x4 thread-local
  red[5] = 2.f*(a[0]*a[4] + a[1]*a[5] + a[2]*a[6] + a[3]*a[7]);
  red[6] = 2.f*(a[0]*a[2] + a[1]*a[3] + a[4]*a[6] + a[5]*a[7]);
  red[7] = 2.f*(a[0]*a[1] + a[2]*a[3] + a[4]*a[5] + a[6]*a[7]);
  // x5..x9 lane partners
  #pragma unroll
  for (int q = 5; q < NQ; q++) {
    const int m = 1 << (9 - q);
    float s = 0.f;
    #pragma unroll
    for (int k = 0; k < 8; k++) s = fmaf(a[k], __shfl_xor_sync(FULLM, a[k], m), s);
    red[8 + q - 5] = s;
  }

  // Hadamard butterfly on ptot: warp total v + per-lane-wire diffs d5..d9
  float v = ptot, d5, d6, d7, d8v, d9;
  { float p = __shfl_xor_sync(FULLM, v, 16); d5 = v - p; v += p; }
  { d5 += __shfl_xor_sync(FULLM, d5, 8);
    float p = __shfl_xor_sync(FULLM, v, 8);  d6 = v - p; v += p; }
  { d5 += __shfl_xor_sync(FULLM, d5, 4); d6 += __shfl_xor_sync(FULLM, d6, 4);
    float p = __shfl_xor_sync(FULLM, v, 4);  d7 = v - p; v += p; }
  { d5 += __shfl_xor_sync(FULLM, d5, 2); d6 += __shfl_xor_sync(FULLM, d6, 2);
    d7 += __shfl_xor_sync(FULLM, d7, 2);
    float p = __shfl_xor_sync(FULLM, v, 2);  d8v = v - p; v += p; }
  { d5 += __shfl_xor_sync(FULLM, d5, 1); d6 += __shfl_xor_sync(FULLM, d6, 1);
    d7 += __shfl_xor_sync(FULLM, d7, 1); d8v += __shfl_xor_sync(FULLM, d8v, 1);
    float p = __shfl_xor_sync(FULLM, v, 1);  d9 = v - p; v += p; }
  #pragma unroll
  for (int j = 0; j < 13; j++) {
    #pragma unroll
    for (int m = 16; m >= 1; m >>= 1) red[j] += __shfl_xor_sync(FULLM, red[j], m);
  }

  if (lane == 0) {
    r1[w][0] = v;
    r1[w][1] = red[0]; r1[w][2] = red[1]; r1[w][3] = red[2];            // z2,z3,z4
    r1[w][4] = d5; r1[w][5] = d6; r1[w][6] = d7; r1[w][7] = d8v; r1[w][8] = d9;
    r1[w][9]  = red[3]; r1[w][10] = red[4];                             // x0,x1
    r1[w][11] = red[5]; r1[w][12] = red[6]; r1[w][13] = red[7];         // x2,x3,x4
    #pragma unroll
    for (int j = 0; j < 5; j++) r1[w][14 + j] = red[8 + j];             // x5..x9
  }
  __syncthreads();
  if (tid < 20) {
    float s = 0.f;
    if (tid == 0) {        // wire0: sign = warp bit1 (i bit9)
      #pragma unroll
      for (int i = 0; i < 4; i++) s += (i & 2) ? -r1[i][0] : r1[i][0];
      zbs[0] = s;
    } else if (tid == 1) { // wire1: sign = warp bit0 (i bit8)
      #pragma unroll
      for (int i = 0; i < 4; i++) s += (i & 1) ? -r1[i][0] : r1[i][0];
      zbs[1] = s;
    } else if (tid < 10) { // z2..z4 at [1..3], d5..d9 at [4..8]
      #pragma unroll
      for (int i = 0; i < 4; i++) s += r1[i][tid - 1];
      zbs[tid] = s;
    } else {               // x0..x9 at [9..18]
      #pragma unroll
      for (int i = 0; i < 4; i++) s += r1[i][tid - 1];
      xbs[tid - 10] = s;
    }
  }
  __syncthreads();

  // ---- epilogue: out[t][c] = (c<10) ? cos(x)*Zb[c] - sin(x)*Xb[c] : 0 ----
  float4* __restrict__ o4 = (float4*)out;
  #pragma unroll
  for (int j = 0; j < 4; j++) {
    const int idx = idx0 + j * stride;
    if (idx >= total4) break;
    const int c4 = idx & 15;
    float4 o = make_float4(0.f, 0.f, 0.f, 0.f);
    if (c4 < 3) {
      const float4 xv = xv4[j];
      const int q0 = c4 * 4;
      float s0, c0, s1, c1;
      __sincosf(xv.x, &s0, &c0); o.x = c0 * zbs[q0]     - s0 * xbs[q0];
      __sincosf(xv.y, &s1, &c1); o.y = c1 * zbs[q0 + 1] - s1 * xbs[q0 + 1];
      if (c4 < 2) {
        float s2, c2, s3, c3;
        __sincosf(xv.z, &s2, &c2); o.z = c2 * zbs[q0 + 2] - s2 * xbs[q0 + 2];
        __sincosf(xv.w, &s3, &c3); o.w = c3 * zbs[q0 + 3] - s3 * xbs[q0 + 3];
      }
    }
    o4[idx] = o;
  }
}

extern "C" void kernel_launch(void* const* d_in, const int* in_sizes, int n_in,
                              void* d_out, int out_size) {
  const float* x = (const float*)d_in[0];
  const float* params = (const float*)d_in[1];
  if (n_in >= 2 && in_sizes[0] == NL * NQ) {   // robust to input ordering
    params = (const float*)d_in[0];
    x = (const float*)d_in[1];
  }
  const int nTok = out_size / 64;
  hqh_kernel<<<148, 128>>>(x, params, (float*)d_out, nTok);
}

// round 6
// speedup vs baseline: 1.0295x; 1.0295x over previous
#include <cuda_runtime.h>

#define FULLM 0xFFFFFFFFu
#define NQ 10
#define NL 4

// 256 threads, 4 amps/thread. Amp index i (10 bits), wire q <-> bit (9-q).
// Layout A: i = (w<<7)|(k<<5)|lane ; w = tid>>5 (3b) -> wires 0,1,2 ;
//           k (2b, amp slot) -> wires 3,4 (LOCAL) ; lane (5b) -> wires 5..9.
// Layout B: transpose T swaps i-bits (9,4)(8,3)(7,2) -> lane bits 4,3,2 = wires 0,1,2.

__device__ __forceinline__ constexpr int sigma_c(int src) {  // CNOT-ring gather (GF(2)-linear)
  src ^= ((src >> 0) & 1) << 9;  // (9,0)
  src ^= ((src >> 1) & 1) << 0;  // (8,9)
  src ^= ((src >> 2) & 1) << 1;  // (7,8)
  src ^= ((src >> 3) & 1) << 2;  // (6,7)
  src ^= ((src >> 4) & 1) << 3;  // (5,6)
  src ^= ((src >> 5) & 1) << 4;  // (4,5)
  src ^= ((src >> 6) & 1) << 5;  // (3,4)
  src ^= ((src >> 7) & 1) << 6;  // (2,3)
  src ^= ((src >> 8) & 1) << 7;  // (1,2)
  src ^= ((src >> 9) & 1) << 8;  // (0,1)
  return src;
}
__device__ __forceinline__ constexpr int T_c(int x) {  // swap bits (9,4)(8,3)(7,2)
  return (x & ~0x39C) | ((x & 0x380) >> 5) | ((x & 0x1C) << 5);
}
__device__ __forceinline__ constexpr int swz(int j) { return j ^ ((j >> 5) & 31); }
__device__ __forceinline__ constexpr int SWK(int k) { return swz(k << 5); }          // = (k<<5)^k
__device__ __forceinline__ constexpr int SGK(int k) { return swz(sigma_c(k << 5)); }

__global__ void __launch_bounds__(256)
hqh_kernel(const float* __restrict__ x,
           const float* __restrict__ params,
           float* __restrict__ out,
           int nTok)
{
  __shared__ float bufA[1024], bufB[1024];
  __shared__ float pc[NL * NQ], ps[NL * NQ];
  __shared__ float r1[8][18];
  __shared__ float zbs[NQ], xbs[NQ];

  const int tid  = threadIdx.x;
  const int lane = tid & 31;
  const int w    = tid >> 5;   // 3 bits -> wires 0,1,2

  if (tid < NL * NQ) {
    float s, c;
    __sincosf(0.5f * params[tid], &s, &c);
    pc[tid] = c; ps[tid] = s;
  }

  // prologue: x load issued early, latency hidden under prep
  const int total4 = nTok * 16;
  const int idx = blockIdx.x * blockDim.x + tid;
  float4 xv4 = make_float4(0.f, 0.f, 0.f, 0.f);
  if (idx < total4 && (idx & 15) < 3) xv4 = ((const float4*)x)[idx];

  // hoisted GF(2)-linear address bases
  const int iA    = (w << 7) | lane;
  const int sA    = swz(iA);          // layout-A store base
  const int gT    = swz(T_c(iA));     // A->B transpose gather base (also B store base)
  const int sigAi = sigma_c(iA);
  const int gS    = swz(sigAi);       // CNOT gather base
  __syncthreads();

  float a[4];
  // ---- layer 0 closed form with its CNOT ring folded in ----
  {
    const int sk[4] = {0, 0x30, 0x60, 0x50};   // sigma(k<<5)
    #pragma unroll
    for (int k = 0; k < 4; k++) {
      const int si = sigAi ^ sk[k];
      float v = 1.f;
      #pragma unroll
      for (int q = 0; q < NQ; q++)
        v *= ((si >> (9 - q)) & 1) ? ps[q] : pc[q];
      a[k] = v;
    }
  }

  #pragma unroll
  for (int l = 1; l < NL; l++) {
    const float* C = pc + l * NQ;
    const float* S = ps + l * NQ;
    const float C0=C[0],S0=S[0],C1=C[1],S1=S[1],C2=C[2],S2=S[2],C3=C[3],S3=S[3],C4=C[4],S4=S[4];
    const float C5=C[5],S5=S[5],C6=C[6],S6=S[6],C7=C[7],S7=S[7],C8=C[8],S8=S[8],C9=C[9],S9=S[9];

    // local wire 3 (k bit1): pairs (0,2),(1,3)
    {
      float l0 = a[0], h0 = a[2], l1 = a[1], h1 = a[3];
      a[0] = C3 * l0 - S3 * h0;  a[2] = fmaf(S3, l0, C3 * h0);
      a[1] = C3 * l1 - S3 * h1;  a[3] = fmaf(S3, l1, C3 * h1);
    }
    // local wire 4 (k bit0): pairs (0,1),(2,3)
    {
      float l0 = a[0], h0 = a[1], l1 = a[2], h1 = a[3];
      a[0] = C4 * l0 - S4 * h0;  a[1] = fmaf(S4, l0, C4 * h0);
      a[2] = C4 * l1 - S4 * h1;  a[3] = fmaf(S4, l1, C4 * h1);
    }
    // lane wires (5,6) fused rank-4 (masks 16,8)
    {
      const float sA5 = (lane & 16) ? S5 : -S5;
      const float sB6 = (lane & 8)  ? S6 : -S6;
      const float k00 = C5 * C6, k01 = C5 * sB6, k10 = sA5 * C6, k11 = sA5 * sB6;
      #pragma unroll
      for (int k = 0; k < 4; k++) {
        float vB  = __shfl_xor_sync(FULLM, a[k], 8);
        float vA  = __shfl_xor_sync(FULLM, a[k], 16);
        float vAB = __shfl_xor_sync(FULLM, a[k], 24);
        a[k] = fmaf(k00, a[k], fmaf(k01, vB, fmaf(k10, vA, k11 * vAB)));
      }
    }
    // lane wires (7,8) fused rank-4 (masks 4,2)
    {
      const float sA7 = (lane & 4) ? S7 : -S7;
      const float sB8 = (lane & 2) ? S8 : -S8;
      const float k00 = C7 * C8, k01 = C7 * sB8, k10 = sA7 * C8, k11 = sA7 * sB8;
      #pragma unroll
      for (int k = 0; k < 4; k++) {
        float vB  = __shfl_xor_sync(FULLM, a[k], 2);
        float vA  = __shfl_xor_sync(FULLM, a[k], 4);
        float vAB = __shfl_xor_sync(FULLM, a[k], 6);
        a[k] = fmaf(k00, a[k], fmaf(k01, vB, fmaf(k10, vA, k11 * vAB)));
      }
    }
    // lane wire 9 (mask 1)
    {
      const float se = (lane & 1) ? S9 : -S9;
      #pragma unroll
      for (int k = 0; k < 4; k++) {
        float p = __shfl_xor_sync(FULLM, a[k], 1);
        a[k] = fmaf(C9, a[k], se * p);
      }
    }
    // exchange A -> B (transpose)
    #pragma unroll
    for (int k = 0; k < 4; k++) bufA[sA ^ SWK(k)] = a[k];
    __syncthreads();
    #pragma unroll
    for (int k = 0; k < 4; k++) a[k] = bufA[gT ^ SWK(k)];   // T fixes bits 6,5
    // layout B: wires (0,1) fused rank-4 (lane masks 16,8)
    {
      const float sA0 = (lane & 16) ? S0 : -S0;
      const float sB1 = (lane & 8)  ? S1 : -S1;
      const float k00 = C0 * C1, k01 = C0 * sB1, k10 = sA0 * C1, k11 = sA0 * sB1;
      #pragma unroll
      for (int k = 0; k < 4; k++) {
        float vB  = __shfl_xor_sync(FULLM, a[k], 8);
        float vA  = __shfl_xor_sync(FULLM, a[k], 16);
        float vAB = __shfl_xor_sync(FULLM, a[k], 24);
        a[k] = fmaf(k00, a[k], fmaf(k01, vB, fmaf(k10, vA, k11 * vAB)));
      }
    }
    // layout B: wire 2 (lane mask 4)
    {
      const float se = (lane & 4) ? S2 : -S2;
      #pragma unroll
      for (int k = 0; k < 4; k++) {
        float p = __shfl_xor_sync(FULLM, a[k], 4);
        a[k] = fmaf(C2, a[k], se * p);
      }
    }
    // exchange B -> A with CNOT ring folded (store by amp index, gather via sigma)
    #pragma unroll
    for (int k = 0; k < 4; k++) bufB[gT ^ SWK(k)] = a[k];
    __syncthreads();
    #pragma unroll
    for (int k = 0; k < 4; k++) a[k] = bufB[gS ^ SGK(k)];
  }

  // ---- observables ----
  float p4[4];
  #pragma unroll
  for (int k = 0; k < 4; k++) p4[k] = a[k] * a[k];
  const float ptot = p4[0] + p4[1] + p4[2] + p4[3];

  float red[12];
  red[0] = (p4[0] + p4[1]) - (p4[2] + p4[3]);                 // z3 (k bit1)
  red[1] = (p4[0] + p4[2]) - (p4[1] + p4[3]);                 // z4 (k bit0)
  // x0,x1,x2 partners via bufB (flip amp bits 9,8,7 -> constexpr swz(sigma(m)) offsets)
  {
    float x0p = 0.f, x1p = 0.f, x2p = 0.f;
    #pragma unroll
    for (int k = 0; k < 4; k++) {
      const int b = gS ^ SGK(k);
      x0p = fmaf(a[k], bufB[b ^ 0x318], x0p);   // swz(sigma(0x200)=0x300)
      x1p = fmaf(a[k], bufB[b ^ 0x18C], x1p);   // swz(sigma(0x100)=0x180)
      x2p = fmaf(a[k], bufB[b ^ 0x0C6], x2p);   // swz(sigma(0x080)=0x0C0)
    }
    red[2] = x0p; red[3] = x1p; red[4] = x2p;
  }
  red[5] = 2.f * (a[0] * a[2] + a[1] * a[3]);                 // x3
  red[6] = 2.f * (a[0] * a[1] + a[2] * a[3]);                 // x4
  #pragma unroll
  for (int q = 5; q < NQ; q++) {                              // x5..x9
    const int m = 1 << (9 - q);
    float s = 0.f;
    #pragma unroll
    for (int k = 0; k < 4; k++) s = fmaf(a[k], __shfl_xor_sync(FULLM, a[k], m), s);
    red[7 + q - 5] = s;
  }

  // Hadamard butterfly on ptot: v = warp total, d5..d9 = per-lane-wire diffs
  float v = ptot, d5, d6, d7, d8v, d9;
  { float p = __shfl_xor_sync(FULLM, v, 16); d5 = v - p; v += p; }
  { d5 += __shfl_xor_sync(FULLM, d5, 8);
    float p = __shfl_xor_sync(FULLM, v, 8);  d6 = v - p; v += p; }
  { d5 += __shfl_xor_sync(FULLM, d5, 4); d6 += __shfl_xor_sync(FULLM, d6, 4);
    float p = __shfl_xor_sync(FULLM, v, 4);  d7 = v - p; v += p; }
  { d5 += __shfl_xor_sync(FULLM, d5, 2); d6 += __shfl_xor_sync(FULLM, d6, 2);
    d7 += __shfl_xor_sync(FULLM, d7, 2);
    float p = __shfl_xor_sync(FULLM, v, 2);  d8v = v - p; v += p; }
  { d5 += __shfl_xor_sync(FULLM, d5, 1); d6 += __shfl_xor_sync(FULLM, d6, 1);
    d7 += __shfl_xor_sync(FULLM, d7, 1); d8v += __shfl_xor_sync(FULLM, d8v, 1);
    float p = __shfl_xor_sync(FULLM, v, 1);  d9 = v - p; v += p; }
  #pragma unroll
  for (int j = 0; j < 12; j++) {
    #pragma unroll
    for (int m = 16; m >= 1; m >>= 1) red[j] += __shfl_xor_sync(FULLM, red[j], m);
  }

  if (lane == 0) {
    r1[w][0] = v;
    r1[w][1] = d5; r1[w][2] = d6; r1[w][3] = d7; r1[w][4] = d8v; r1[w][5] = d9;
    r1[w][6] = red[0]; r1[w][7] = red[1];          // z3, z4
    #pragma unroll
    for (int j = 0; j < 10; j++) r1[w][8 + j] = red[2 + j];   // x0..x9
  }
  __syncthreads();
  if (tid < 20) {
    float s = 0.f;
    if (tid < 3) {           // z0,z1,z2: sign = warp bit (2-tid)
      const int sb = 1 << (2 - tid);
      #pragma unroll
      for (int i = 0; i < 8; i++) s += (i & sb) ? -r1[i][0] : r1[i][0];
      zbs[tid] = s;
    } else if (tid < 5) {    // z3,z4 at j6,j7
      #pragma unroll
      for (int i = 0; i < 8; i++) s += r1[i][tid + 3];
      zbs[tid] = s;
    } else if (tid < 10) {   // z5..z9 at j1..j5
      #pragma unroll
      for (int i = 0; i < 8; i++) s += r1[i][tid - 4];
      zbs[tid] = s;
    } else {                 // x0..x9 at j8..j17
      #pragma unroll
      for (int i = 0; i < 8; i++) s += r1[i][tid - 2];
      xbs[tid - 10] = s;
    }
  }
  __syncthreads();

  // ---- epilogue: out[t][c] = (c<10) ? cos(x)*Zb[c] - sin(x)*Xb[c] : 0 ----
  if (idx < total4) {
    const int c4 = idx & 15;
    float4 o = make_float4(0.f, 0.f, 0.f, 0.f);
    if (c4 < 3) {
      const int q0 = c4 * 4;
      float s0, c0, s1, c1;
      __sincosf(xv4.x, &s0, &c0); o.x = c0 * zbs[q0]     - s0 * xbs[q0];
      __sincosf(xv4.y, &s1, &c1); o.y = c1 * zbs[q0 + 1] - s1 * xbs[q0 + 1];
      if (c4 < 2) {
        float s2, c2, s3, c3;
        __sincosf(xv4.z, &s2, &c2); o.z = c2 * zbs[q0 + 2] - s2 * xbs[q0 + 2];
        __sincosf(xv4.w, &s3, &c3); o.w = c3 * zbs[q0 + 3] - s3 * xbs[q0 + 3];
      }
    }
    ((float4*)out)[idx] = o;
  }
}

extern "C" void kernel_launch(void* const* d_in, const int* in_sizes, int n_in,
                              void* d_out, int out_size) {
  const float* x = (const float*)d_in[0];
  const float* params = (const float*)d_in[1];
  if (n_in >= 2 && in_sizes[0] == NL * NQ) {   // robust to input ordering
    params = (const float*)d_in[0];
    x = (const float*)d_in[1];
  }
  const int nTok = out_size / 64;
  const int total4 = nTok * 16;
  int grid = (total4 + 255) / 256;
  if (grid < 1) grid = 1;
  hqh_kernel<<<grid, 256>>>(x, params, (float*)d_out, nTok);
}